// round 5
// baseline (speedup 1.0000x reference)
#include <cuda_runtime.h>
#include <math.h>
#include <stdint.h>

#define BDIM 4096
#define DDIM 1024
#define KSEL 1024
#define EPSV 1e-6f
#define MARGINV 0.5f
#define BIGV 1.0e6f

// ---------------- scratch (device globals; allocation-free) ----------------
__device__ float g_dist[(size_t)BDIM * BDIM];   // 64 MB
__device__ float g_distT[(size_t)BDIM * BDIM];  // 64 MB
__device__ float g_xr[(size_t)BDIM * DDIM];     // tf32-rounded X (16 MB)
__device__ float g_yr[(size_t)BDIM * DDIM];     // tf32-rounded Y (16 MB)
__device__ float g_nx[BDIM];
__device__ float g_ny[BDIM];
__device__ float g_sy[BDIM];
__device__ float g_rl[2 * BDIM];

// ---------------- helpers ----------------
__device__ __forceinline__ uint32_t smem_u32(const void* p) {
    uint32_t a;
    asm("{ .reg .u64 t; cvta.to.shared.u64 t, %1; cvt.u32.u64 %0, t; }" : "=r"(a) : "l"(p));
    return a;
}
__device__ __forceinline__ void cp16(void* dst, const void* src) {
    uint32_t d = smem_u32(dst);
    asm volatile("cp.async.cg.shared.global [%0], [%1], 16;" :: "r"(d), "l"(src));
}
#define CP_COMMIT() asm volatile("cp.async.commit_group;")
#define CP_WAIT1()  asm volatile("cp.async.wait_group 1;")

__device__ __forceinline__ float tf32_rna(float v) {
    uint32_t r;
    asm("cvt.rna.tf32.f32 %0, %1;" : "=r"(r) : "f"(v));
    return __uint_as_float(r);
}

__device__ __forceinline__ void mma_tf32(float* c, const uint32_t* a, const uint32_t* b) {
    asm volatile(
        "mma.sync.aligned.m16n8k8.row.col.f32.tf32.tf32.f32 "
        "{%0,%1,%2,%3}, {%4,%5,%6,%7}, {%8,%9}, {%0,%1,%2,%3};"
        : "+f"(c[0]), "+f"(c[1]), "+f"(c[2]), "+f"(c[3])
        : "r"(a[0]), "r"(a[1]), "r"(a[2]), "r"(a[3]), "r"(b[0]), "r"(b[1]));
}

// Warp-aggregated histogram add: one atomic per distinct digit per warp.
__device__ __forceinline__ void agg_hist_add(unsigned* hist, unsigned digit, bool active) {
    const unsigned ball = __ballot_sync(0xFFFFFFFFu, active);
    const unsigned peers = __match_any_sync(0xFFFFFFFFu, digit) & ball;
    if (active) {
        const unsigned lane = threadIdx.x & 31;
        if (lane == (unsigned)(__ffs(peers) - 1))
            atomicAdd(&hist[digit], __popc(peers));
    }
}

// ---------------- GEMM config (exact round-3 configuration) ----------------
#define BM 128
#define BN 128
#define BK 32
#define PITCH 36                          // floats; conflict-free frag reads
#define STAGE_FLOATS (2 * 128 * PITCH)    // A+B per stage = 9216 floats (36 KB)
#define GEMM_SMEM (2 * STAGE_FLOATS * 4)  // 73728 bytes

// ---------------------------------------------------------------------------
// Norms + tf32 pre-rounding (one float4 per thread):
//   nx[i]=||x_i+eps||^2, ny[j]=||y_j||^2, sy[j]=sum(y_j);
//   g_xr = rna_tf32(X), g_yr = rna_tf32(Y)
// ---------------------------------------------------------------------------
__global__ void __launch_bounds__(256) norms_kernel(const float* __restrict__ X,
                                                    const float* __restrict__ Y) {
    __shared__ float s1[256], s2[256];
    const int row = blockIdx.x;
    const int isY = blockIdx.y;
    const int tid = threadIdx.x;
    const float4* p4 = (const float4*)((isY ? Y : X) + (size_t)row * DDIM);
    float4* pr4 = (float4*)((isY ? g_yr : g_xr) + (size_t)row * DDIM);

    float4 v = p4[tid];
    float4 r;
    r.x = tf32_rna(v.x); r.y = tf32_rna(v.y); r.z = tf32_rna(v.z); r.w = tf32_rna(v.w);
    pr4[tid] = r;

    float a, b = 0.0f;
    if (isY) {
        a = v.x * v.x + v.y * v.y + v.z * v.z + v.w * v.w;
        b = v.x + v.y + v.z + v.w;
    } else {
        float ex = v.x + EPSV, ey = v.y + EPSV, ez = v.z + EPSV, ew = v.w + EPSV;
        a = ex * ex + ey * ey + ez * ez + ew * ew;
    }
    s1[tid] = a; s2[tid] = b;
    __syncthreads();
    for (int off = 128; off; off >>= 1) {
        if (tid < off) { s1[tid] += s1[tid + off]; s2[tid] += s2[tid + off]; }
        __syncthreads();
    }
    if (tid == 0) {
        if (isY) { g_ny[row] = s1[0]; g_sy[row] = s2[0]; }
        else     { g_nx[row] = s1[0]; }
    }
}

// ---------------------------------------------------------------------------
// tf32 mma.sync GEMM + distance epilogue (writes dist AND distT).
// 128x128 tile/CTA, 8 warps (4x2), warp tile 32x64, cp.async double buffer.
// (identical to round-3 version)
// ---------------------------------------------------------------------------
__device__ __forceinline__ void issue_stage(float* sA, float* sB,
                                            const float* gA, const float* gB, int tid) {
#pragma unroll
    for (int i = 0; i < 4; i++) {
        const int idx = tid + i * 256;      // 0..1023
        const int r = idx >> 3;             // row 0..127
        const int c = (idx & 7) * 4;        // float col 0,4,..,28
        cp16(sA + r * PITCH + c, gA + (size_t)r * DDIM + c);
        cp16(sB + r * PITCH + c, gB + (size_t)r * DDIM + c);
    }
}

__global__ void __launch_bounds__(256, 2) gemm_mma_kernel() {
    extern __shared__ float smf[];
    const int tid = threadIdx.x;
    const int wid = tid >> 5;
    const int lane = tid & 31;
    const int wm = wid & 3;          // warp row 0..3  (32 rows each)
    const int wn = wid >> 2;         // warp col 0..1  (64 cols each)
    const int g = lane >> 2;         // 0..7
    const int t = lane & 3;          // 0..3
    const int bi = blockIdx.y * BM;
    const int bj = blockIdx.x * BN;

    const float* gA = g_xr + (size_t)bi * DDIM;
    const float* gB = g_yr + (size_t)bj * DDIM;

    float acc[2][8][4];
#pragma unroll
    for (int mi = 0; mi < 2; mi++)
#pragma unroll
        for (int ni = 0; ni < 8; ni++)
#pragma unroll
            for (int e = 0; e < 4; e++) acc[mi][ni][e] = 0.0f;

    // prologue: two stages in flight
    issue_stage(smf, smf + 128 * PITCH, gA, gB, tid);
    CP_COMMIT();
    issue_stage(smf + STAGE_FLOATS, smf + STAGE_FLOATS + 128 * PITCH,
                gA + BK, gB + BK, tid);
    CP_COMMIT();

    const int NCHUNK = DDIM / BK;    // 32
    for (int c = 0; c < NCHUNK; c++) {
        const int buf = c & 1;
        CP_WAIT1();
        __syncthreads();
        const uint32_t* sA = (const uint32_t*)(smf + buf * STAGE_FLOATS);
        const uint32_t* sB = sA + 128 * PITCH;

#pragma unroll
        for (int ks = 0; ks < 4; ks++) {
            const int k0 = ks * 8;
            uint32_t a[2][4], b[8][2];
#pragma unroll
            for (int mi = 0; mi < 2; mi++) {
                const int r0 = wm * 32 + mi * 16;
                a[mi][0] = sA[(r0 + g) * PITCH + k0 + t];
                a[mi][1] = sA[(r0 + g + 8) * PITCH + k0 + t];
                a[mi][2] = sA[(r0 + g) * PITCH + k0 + t + 4];
                a[mi][3] = sA[(r0 + g + 8) * PITCH + k0 + t + 4];
            }
#pragma unroll
            for (int ni = 0; ni < 8; ni++) {
                const int c0 = wn * 64 + ni * 8;
                b[ni][0] = sB[(c0 + g) * PITCH + k0 + t];
                b[ni][1] = sB[(c0 + g) * PITCH + k0 + t + 4];
            }
#pragma unroll
            for (int mi = 0; mi < 2; mi++)
#pragma unroll
                for (int ni = 0; ni < 8; ni++)
                    mma_tf32(acc[mi][ni], a[mi], b[ni]);
        }
        __syncthreads();
        if (c + 2 < NCHUNK)
            issue_stage(smf + buf * STAGE_FLOATS,
                        smf + buf * STAGE_FLOATS + 128 * PITCH,
                        gA + (c + 2) * BK, gB + (c + 2) * BK, tid);
        CP_COMMIT();
    }

    // -------- epilogue: regs -> smem tile (pitch 129) -> dist & distT --------
    __syncthreads();
    float* tile = smf;                       // 128 x 129
    float* nx_s = smf + 128 * 129;
    float* ny_s = nx_s + 128;
    float* sy_s = ny_s + 128;
    if (tid < 128) {
        nx_s[tid] = g_nx[bi + tid];
        ny_s[tid] = g_ny[bj + tid];
        sy_s[tid] = g_sy[bj + tid];
    }
    __syncthreads();

#pragma unroll
    for (int mi = 0; mi < 2; mi++) {
        const int r0 = wm * 32 + mi * 16 + g;
#pragma unroll
        for (int ni = 0; ni < 8; ni++) {
            const int c0 = wn * 64 + ni * 8 + 2 * t;
#pragma unroll
            for (int e = 0; e < 4; e++) {
                const int row = r0 + (e >> 1) * 8;
                const int col = c0 + (e & 1);
                float sq = nx_s[row] + ny_s[col] - 2.0f * acc[mi][ni][e]
                           - 2.0f * EPSV * sy_s[col];
                tile[row * 129 + col] = sqrtf(fmaxf(sq, 0.0f));
            }
        }
    }
    __syncthreads();

    // dist: coalesced float4 row writes
    for (int i = tid; i < 128 * 32; i += 256) {
        const int rr = i >> 5;
        const int c4 = (i & 31) << 2;
        float4 v;
        v.x = tile[rr * 129 + c4 + 0];
        v.y = tile[rr * 129 + c4 + 1];
        v.z = tile[rr * 129 + c4 + 2];
        v.w = tile[rr * 129 + c4 + 3];
        *(float4*)&g_dist[(size_t)(bi + rr) * BDIM + bj + c4] = v;
    }
    // distT: conflict-free column reads (pitch 129), coalesced row writes
    for (int i = tid; i < 128 * 128; i += 256) {
        const int rr = i & 127;
        const int cc = i >> 7;
        g_distT[(size_t)(bj + cc) * BDIM + bi + rr] = tile[rr * 129 + cc];
    }
}

// ---------------------------------------------------------------------------
// Per-row loss, exact K-th order statistic via MSB radix select.
// Warp-aggregated histogram atomics (distance digits are highly skewed),
// pass-0 hist fused with the count sweep, parallel scan for digit pick.
// grid (BDIM, 2): y=0 rows of dist (loss_xy), y=1 rows of distT (loss_yx).
// ---------------------------------------------------------------------------
__global__ void __launch_bounds__(256) select_kernel() {
    __shared__ float vals[BDIM];
    __shared__ unsigned hist[256];
    __shared__ unsigned scan[256];
    __shared__ float red_f[256];
    __shared__ unsigned red_u[256];
    __shared__ float s_t;
    __shared__ unsigned s_prefix, s_remk;

    const int row = blockIdx.x;
    const int tid = threadIdx.x;
    const float* mat = blockIdx.y ? g_distT : g_dist;
    float* rl = g_rl + blockIdx.y * BDIM;
    const float4* rp4 = (const float4*)(mat + (size_t)row * BDIM);
    float4* v4 = (float4*)vals;

    for (int i = tid; i < BDIM / 4; i += 256) v4[i] = rp4[i];
    hist[tid] = 0;
    __syncthreads();
    if (tid == 0) {
        s_t = MARGINV + vals[row];
        vals[row] = BIGV;
    }
    __syncthreads();
    const float t = s_t;

    // fused sweep: hinge count/sum against t AND pass-0 histogram (bits 31:24)
    unsigned c = 0; float s = 0.0f;
    for (int i = tid; i < BDIM; i += 256) {
        const float v = vals[i];
        if (v < t) { c++; s += t - v; }
        agg_hist_add(hist, __float_as_uint(v) >> 24, true);
    }
    red_u[tid] = c; red_f[tid] = s;
    __syncthreads();
    for (int off = 128; off; off >>= 1) {
        if (tid < off) { red_u[tid] += red_u[tid + off]; red_f[tid] += red_f[tid + off]; }
        __syncthreads();
    }
    const unsigned ctot = red_u[0];
    const float sall = red_f[0];
    __syncthreads();

    if (ctot <= KSEL) {
        if (tid == 0) rl[row] = sall;
        return;
    }

    unsigned prefix = 0, remk = KSEL;
#pragma unroll
    for (int pass = 0; pass < 4; pass++) {
        const int shift = 24 - 8 * pass;
        // parallel inclusive scan of hist
        scan[tid] = hist[tid];
        __syncthreads();
#pragma unroll
        for (int off = 1; off < 256; off <<= 1) {
            unsigned y = (tid >= off) ? scan[tid - off] : 0u;
            __syncthreads();
            scan[tid] += y;
            __syncthreads();
        }
        const unsigned excl = tid ? scan[tid - 1] : 0u;
        if (scan[tid] >= remk && excl < remk) {
            s_prefix = prefix | ((unsigned)tid << shift);
            s_remk = remk - excl;
        }
        __syncthreads();
        prefix = s_prefix; remk = s_remk;

        if (pass < 3) {
            const int nshift = shift - 8;
            const unsigned pmask = 0xFFFFFFFFu << shift;
            hist[tid] = 0;
            __syncthreads();
            for (int i = tid; i < BDIM; i += 256) {
                const unsigned b = __float_as_uint(vals[i]);
                agg_hist_add(hist, (b >> nshift) & 255u, (b & pmask) == prefix);
            }
            __syncthreads();
        }
    }
    const float theta = __uint_as_float(prefix);

    // sum/count strictly below theta; ties at theta fill to K
    unsigned cl = 0; float sl = 0.0f;
    for (int i = tid; i < BDIM; i += 256) {
        const float v = vals[i];
        if (v < theta) { cl++; sl += v; }
    }
    red_u[tid] = cl; red_f[tid] = sl;
    __syncthreads();
    for (int off = 128; off; off >>= 1) {
        if (tid < off) { red_u[tid] += red_u[tid + off]; red_f[tid] += red_f[tid + off]; }
        __syncthreads();
    }
    if (tid == 0)
        rl[row] = (float)KSEL * t - red_f[0] - (float)(KSEL - red_u[0]) * theta;
}

__global__ void finalize_kernel(float* __restrict__ out) {
    __shared__ float sm[256];
    for (int which = 0; which < 2; which++) {
        float s = 0.0f;
        for (int i = threadIdx.x; i < BDIM; i += 256) s += g_rl[which * BDIM + i];
        sm[threadIdx.x] = s;
        __syncthreads();
        for (int off = 128; off; off >>= 1) {
            if (threadIdx.x < off) sm[threadIdx.x] += sm[threadIdx.x + off];
            __syncthreads();
        }
        if (threadIdx.x == 0) out[which] = sm[0] / ((float)BDIM * (float)KSEL);
        __syncthreads();
    }
}

// ---------------------------------------------------------------------------
extern "C" void kernel_launch(void* const* d_in, const int* in_sizes, int n_in,
                              void* d_out, int out_size) {
    const float* X = (const float*)d_in[0];
    const float* Y = (const float*)d_in[1];
    float* out = (float*)d_out;

    cudaFuncSetAttribute(gemm_mma_kernel, cudaFuncAttributeMaxDynamicSharedMemorySize,
                         GEMM_SMEM);

    norms_kernel<<<dim3(BDIM, 2), 256>>>(X, Y);
    gemm_mma_kernel<<<dim3(BDIM / BN, BDIM / BM), 256, GEMM_SMEM>>>();
    select_kernel<<<dim3(BDIM, 2), 256>>>();
    finalize_kernel<<<1, 256>>>(out);
}

// round 6
// speedup vs baseline: 2.1193x; 2.1193x over previous
#include <cuda_runtime.h>
#include <math.h>
#include <stdint.h>

#define BDIM 4096
#define DDIM 1024
#define KSEL 1024
#define EPSV 1e-6f
#define MARGINV 0.5f
#define BIGV 1.0e6f

// ---------------- scratch (device globals; allocation-free) ----------------
__device__ float g_dist[(size_t)BDIM * BDIM];   // 64 MB
__device__ float g_distT[(size_t)BDIM * BDIM];  // 64 MB
__device__ float g_xr[(size_t)BDIM * DDIM];     // tf32-rounded X (16 MB)
__device__ float g_yr[(size_t)BDIM * DDIM];     // tf32-rounded Y (16 MB)
__device__ float g_nx[BDIM];
__device__ float g_ny[BDIM];
__device__ float g_sy[BDIM];
__device__ float g_rl[2 * BDIM];

// ---------------- helpers ----------------
__device__ __forceinline__ uint32_t smem_u32(const void* p) {
    uint32_t a;
    asm("{ .reg .u64 t; cvta.to.shared.u64 t, %1; cvt.u32.u64 %0, t; }" : "=r"(a) : "l"(p));
    return a;
}
__device__ __forceinline__ void cp16(void* dst, const void* src) {
    uint32_t d = smem_u32(dst);
    asm volatile("cp.async.cg.shared.global [%0], [%1], 16;" :: "r"(d), "l"(src));
}
#define CP_COMMIT() asm volatile("cp.async.commit_group;")
#define CP_WAIT1()  asm volatile("cp.async.wait_group 1;")

__device__ __forceinline__ float tf32_rna(float v) {
    uint32_t r;
    asm("cvt.rna.tf32.f32 %0, %1;" : "=r"(r) : "f"(v));
    return __uint_as_float(r);
}

__device__ __forceinline__ void mma_tf32(float* c, const uint32_t* a, const uint32_t* b) {
    asm volatile(
        "mma.sync.aligned.m16n8k8.row.col.f32.tf32.tf32.f32 "
        "{%0,%1,%2,%3}, {%4,%5,%6,%7}, {%8,%9}, {%0,%1,%2,%3};"
        : "+f"(c[0]), "+f"(c[1]), "+f"(c[2]), "+f"(c[3])
        : "r"(a[0]), "r"(a[1]), "r"(a[2]), "r"(a[3]), "r"(b[0]), "r"(b[1]));
}

// ---------------- GEMM config (exact round-3 configuration) ----------------
#define BM 128
#define BN 128
#define BK 32
#define PITCH 36                          // floats; conflict-free frag reads
#define STAGE_FLOATS (2 * 128 * PITCH)    // A+B per stage = 9216 floats (36 KB)
#define GEMM_SMEM (2 * STAGE_FLOATS * 4)  // 73728 bytes

// ---------------------------------------------------------------------------
// Norms + tf32 pre-rounding (one float4 per thread)
// ---------------------------------------------------------------------------
__global__ void __launch_bounds__(256) norms_kernel(const float* __restrict__ X,
                                                    const float* __restrict__ Y) {
    __shared__ float s1[256], s2[256];
    const int row = blockIdx.x;
    const int isY = blockIdx.y;
    const int tid = threadIdx.x;
    const float4* p4 = (const float4*)((isY ? Y : X) + (size_t)row * DDIM);
    float4* pr4 = (float4*)((isY ? g_yr : g_xr) + (size_t)row * DDIM);

    float4 v = p4[tid];
    float4 r;
    r.x = tf32_rna(v.x); r.y = tf32_rna(v.y); r.z = tf32_rna(v.z); r.w = tf32_rna(v.w);
    pr4[tid] = r;

    float a, b = 0.0f;
    if (isY) {
        a = v.x * v.x + v.y * v.y + v.z * v.z + v.w * v.w;
        b = v.x + v.y + v.z + v.w;
    } else {
        float ex = v.x + EPSV, ey = v.y + EPSV, ez = v.z + EPSV, ew = v.w + EPSV;
        a = ex * ex + ey * ey + ez * ez + ew * ew;
    }
    s1[tid] = a; s2[tid] = b;
    __syncthreads();
    for (int off = 128; off; off >>= 1) {
        if (tid < off) { s1[tid] += s1[tid + off]; s2[tid] += s2[tid + off]; }
        __syncthreads();
    }
    if (tid == 0) {
        if (isY) { g_ny[row] = s1[0]; g_sy[row] = s2[0]; }
        else     { g_nx[row] = s1[0]; }
    }
}

// ---------------------------------------------------------------------------
// tf32 mma.sync GEMM + distance epilogue (writes dist AND distT).
// 128x128 tile/CTA, 8 warps (4x2), warp tile 32x64, cp.async double buffer.
// (identical to round-3 version)
// ---------------------------------------------------------------------------
__device__ __forceinline__ void issue_stage(float* sA, float* sB,
                                            const float* gA, const float* gB, int tid) {
#pragma unroll
    for (int i = 0; i < 4; i++) {
        const int idx = tid + i * 256;      // 0..1023
        const int r = idx >> 3;             // row 0..127
        const int c = (idx & 7) * 4;        // float col 0,4,..,28
        cp16(sA + r * PITCH + c, gA + (size_t)r * DDIM + c);
        cp16(sB + r * PITCH + c, gB + (size_t)r * DDIM + c);
    }
}

__global__ void __launch_bounds__(256, 2) gemm_mma_kernel() {
    extern __shared__ float smf[];
    const int tid = threadIdx.x;
    const int wid = tid >> 5;
    const int lane = tid & 31;
    const int wm = wid & 3;          // warp row 0..3  (32 rows each)
    const int wn = wid >> 2;         // warp col 0..1  (64 cols each)
    const int g = lane >> 2;         // 0..7
    const int t = lane & 3;          // 0..3
    const int bi = blockIdx.y * BM;
    const int bj = blockIdx.x * BN;

    const float* gA = g_xr + (size_t)bi * DDIM;
    const float* gB = g_yr + (size_t)bj * DDIM;

    float acc[2][8][4];
#pragma unroll
    for (int mi = 0; mi < 2; mi++)
#pragma unroll
        for (int ni = 0; ni < 8; ni++)
#pragma unroll
            for (int e = 0; e < 4; e++) acc[mi][ni][e] = 0.0f;

    // prologue: two stages in flight
    issue_stage(smf, smf + 128 * PITCH, gA, gB, tid);
    CP_COMMIT();
    issue_stage(smf + STAGE_FLOATS, smf + STAGE_FLOATS + 128 * PITCH,
                gA + BK, gB + BK, tid);
    CP_COMMIT();

    const int NCHUNK = DDIM / BK;    // 32
    for (int c = 0; c < NCHUNK; c++) {
        const int buf = c & 1;
        CP_WAIT1();
        __syncthreads();
        const uint32_t* sA = (const uint32_t*)(smf + buf * STAGE_FLOATS);
        const uint32_t* sB = sA + 128 * PITCH;

#pragma unroll
        for (int ks = 0; ks < 4; ks++) {
            const int k0 = ks * 8;
            uint32_t a[2][4], b[8][2];
#pragma unroll
            for (int mi = 0; mi < 2; mi++) {
                const int r0 = wm * 32 + mi * 16;
                a[mi][0] = sA[(r0 + g) * PITCH + k0 + t];
                a[mi][1] = sA[(r0 + g + 8) * PITCH + k0 + t];
                a[mi][2] = sA[(r0 + g) * PITCH + k0 + t + 4];
                a[mi][3] = sA[(r0 + g + 8) * PITCH + k0 + t + 4];
            }
#pragma unroll
            for (int ni = 0; ni < 8; ni++) {
                const int c0 = wn * 64 + ni * 8;
                b[ni][0] = sB[(c0 + g) * PITCH + k0 + t];
                b[ni][1] = sB[(c0 + g) * PITCH + k0 + t + 4];
            }
#pragma unroll
            for (int mi = 0; mi < 2; mi++)
#pragma unroll
                for (int ni = 0; ni < 8; ni++)
                    mma_tf32(acc[mi][ni], a[mi], b[ni]);
        }
        __syncthreads();
        if (c + 2 < NCHUNK)
            issue_stage(smf + buf * STAGE_FLOATS,
                        smf + buf * STAGE_FLOATS + 128 * PITCH,
                        gA + (c + 2) * BK, gB + (c + 2) * BK, tid);
        CP_COMMIT();
    }

    // -------- epilogue: regs -> smem tile (pitch 129) -> dist & distT --------
    __syncthreads();
    float* tile = smf;                       // 128 x 129
    float* nx_s = smf + 128 * 129;
    float* ny_s = nx_s + 128;
    float* sy_s = ny_s + 128;
    if (tid < 128) {
        nx_s[tid] = g_nx[bi + tid];
        ny_s[tid] = g_ny[bj + tid];
        sy_s[tid] = g_sy[bj + tid];
    }
    __syncthreads();

#pragma unroll
    for (int mi = 0; mi < 2; mi++) {
        const int r0 = wm * 32 + mi * 16 + g;
#pragma unroll
        for (int ni = 0; ni < 8; ni++) {
            const int c0 = wn * 64 + ni * 8 + 2 * t;
#pragma unroll
            for (int e = 0; e < 4; e++) {
                const int row = r0 + (e >> 1) * 8;
                const int col = c0 + (e & 1);
                float sq = nx_s[row] + ny_s[col] - 2.0f * acc[mi][ni][e]
                           - 2.0f * EPSV * sy_s[col];
                tile[row * 129 + col] = sqrtf(fmaxf(sq, 0.0f));
            }
        }
    }
    __syncthreads();

    // dist: coalesced float4 row writes
    for (int i = tid; i < 128 * 32; i += 256) {
        const int rr = i >> 5;
        const int c4 = (i & 31) << 2;
        float4 v;
        v.x = tile[rr * 129 + c4 + 0];
        v.y = tile[rr * 129 + c4 + 1];
        v.z = tile[rr * 129 + c4 + 2];
        v.w = tile[rr * 129 + c4 + 3];
        *(float4*)&g_dist[(size_t)(bi + rr) * BDIM + bj + c4] = v;
    }
    // distT: conflict-free column reads (pitch 129), coalesced row writes
    for (int i = tid; i < 128 * 128; i += 256) {
        const int rr = i & 127;
        const int cc = i >> 7;
        g_distT[(size_t)(bj + cc) * BDIM + bi + rr] = tile[rr * 129 + cc];
    }
}

// ---------------------------------------------------------------------------
// Per-row loss, exact K-th order statistic via MSB radix select.
// R3 structure (plain atomics, serial digit scan) + float4 loads +
// register-cached values for the count and final sweeps.
// grid (BDIM, 2): y=0 rows of dist (loss_xy), y=1 rows of distT (loss_yx).
// ---------------------------------------------------------------------------
__global__ void __launch_bounds__(256) select_kernel() {
    __shared__ float vals[BDIM];
    __shared__ unsigned hist[256];
    __shared__ float red_f[256];
    __shared__ unsigned red_u[256];
    __shared__ float s_t;
    __shared__ unsigned s_prefix, s_remk;

    const int row = blockIdx.x;
    const int tid = threadIdx.x;
    const float* mat = blockIdx.y ? g_distT : g_dist;
    float* rl = g_rl + blockIdx.y * BDIM;
    const float4* rp4 = (const float4*)(mat + (size_t)row * BDIM);
    float4* v4 = (float4*)vals;

    // load row: 4 float4 per thread, kept in registers AND staged to smem
    float4 rv[4];
#pragma unroll
    for (int c = 0; c < 4; c++) {
        const int i = tid + c * 256;       // float4 index 0..1023
        rv[c] = rp4[i];
        v4[i] = rv[c];
    }
    // patch diagonal in the owning thread's register copy
    {
        const int di = row >> 2;           // float4 index of diagonal
        const int dc = di >> 8;            // chunk
        if ((di & 255) == tid) {
            float* f = (float*)&rv[dc];
            f[row & 3] = BIGV;
        }
    }
    __syncthreads();
    if (tid == 0) {
        s_t = MARGINV + vals[row];
        vals[row] = BIGV;
    }
    __syncthreads();
    const float t = s_t;

    // count/sum hinge against t from registers
    unsigned c = 0; float s = 0.0f;
#pragma unroll
    for (int q = 0; q < 4; q++) {
        const float* f = (const float*)&rv[q];
#pragma unroll
        for (int e = 0; e < 4; e++) {
            const float v = f[e];
            if (v < t) { c++; s += t - v; }
        }
    }
    red_u[tid] = c; red_f[tid] = s;
    __syncthreads();
    for (int off = 128; off; off >>= 1) {
        if (tid < off) { red_u[tid] += red_u[tid + off]; red_f[tid] += red_f[tid + off]; }
        __syncthreads();
    }
    const unsigned ctot = red_u[0];
    const float sall = red_f[0];
    __syncthreads();

    if (ctot <= KSEL) {
        if (tid == 0) rl[row] = sall;
        return;
    }

    // MSB radix select (exact R3 logic, smem sweeps, plain atomics)
    unsigned prefix = 0, remk = KSEL;
#pragma unroll
    for (int pass = 0; pass < 4; pass++) {
        const int shift = 24 - 8 * pass;
        hist[tid] = 0;
        __syncthreads();
        const unsigned pmask = (pass == 0) ? 0u : (0xFFFFFFFFu << (shift + 8));
        for (int i = tid; i < BDIM; i += 256) {
            unsigned b = __float_as_uint(vals[i]);
            if ((b & pmask) == prefix) atomicAdd(&hist[(b >> shift) & 255], 1u);
        }
        __syncthreads();
        if (tid == 0) {
            unsigned cum = 0; int d = 0;
            for (; d < 256; d++) { cum += hist[d]; if (cum >= remk) break; }
            s_prefix = prefix | ((unsigned)d << shift);
            s_remk = remk - (cum - hist[d]);
        }
        __syncthreads();
        prefix = s_prefix; remk = s_remk;
        __syncthreads();
    }
    const float theta = __uint_as_float(prefix);

    // sum/count strictly below theta from registers; ties at theta fill to K
    unsigned cl = 0; float sl = 0.0f;
#pragma unroll
    for (int q = 0; q < 4; q++) {
        const float* f = (const float*)&rv[q];
#pragma unroll
        for (int e = 0; e < 4; e++) {
            const float v = f[e];
            if (v < theta) { cl++; sl += v; }
        }
    }
    red_u[tid] = cl; red_f[tid] = sl;
    __syncthreads();
    for (int off = 128; off; off >>= 1) {
        if (tid < off) { red_u[tid] += red_u[tid + off]; red_f[tid] += red_f[tid + off]; }
        __syncthreads();
    }
    if (tid == 0)
        rl[row] = (float)KSEL * t - red_f[0] - (float)(KSEL - red_u[0]) * theta;
}

__global__ void finalize_kernel(float* __restrict__ out) {
    __shared__ float sm[256];
    for (int which = 0; which < 2; which++) {
        float s = 0.0f;
        for (int i = threadIdx.x; i < BDIM; i += 256) s += g_rl[which * BDIM + i];
        sm[threadIdx.x] = s;
        __syncthreads();
        for (int off = 128; off; off >>= 1) {
            if (threadIdx.x < off) sm[threadIdx.x] += sm[threadIdx.x + off];
            __syncthreads();
        }
        if (threadIdx.x == 0) out[which] = sm[0] / ((float)BDIM * (float)KSEL);
        __syncthreads();
    }
}

// ---------------------------------------------------------------------------
extern "C" void kernel_launch(void* const* d_in, const int* in_sizes, int n_in,
                              void* d_out, int out_size) {
    const float* X = (const float*)d_in[0];
    const float* Y = (const float*)d_in[1];
    float* out = (float*)d_out;

    cudaFuncSetAttribute(gemm_mma_kernel, cudaFuncAttributeMaxDynamicSharedMemorySize,
                         GEMM_SMEM);

    norms_kernel<<<dim3(BDIM, 2), 256>>>(X, Y);
    gemm_mma_kernel<<<dim3(BDIM / BN, BDIM / BM), 256, GEMM_SMEM>>>();
    select_kernel<<<dim3(BDIM, 2), 256>>>();
    finalize_kernel<<<1, 256>>>(out);
}

// round 7
// speedup vs baseline: 2.4489x; 1.1555x over previous
#include <cuda_runtime.h>
#include <math.h>
#include <stdint.h>

#define BDIM 4096
#define DDIM 1024
#define KSEL 1024
#define EPSV 1e-6f
#define MARGINV 0.5f
#define BIGV 1.0e6f

// ---------------- scratch (device globals; allocation-free) ----------------
__device__ float g_dist[(size_t)BDIM * BDIM];   // 64 MB
__device__ float g_distT[(size_t)BDIM * BDIM];  // 64 MB
__device__ float g_xr[(size_t)BDIM * DDIM];     // tf32-rounded X (16 MB)
__device__ float g_yr[(size_t)BDIM * DDIM];     // tf32-rounded Y (16 MB)
__device__ float g_nx[BDIM];
__device__ float g_ny[BDIM];
__device__ float g_sy[BDIM];
__device__ float g_rl[2 * BDIM];

// ---------------- helpers ----------------
__device__ __forceinline__ uint32_t smem_u32(const void* p) {
    uint32_t a;
    asm("{ .reg .u64 t; cvta.to.shared.u64 t, %1; cvt.u32.u64 %0, t; }" : "=r"(a) : "l"(p));
    return a;
}
__device__ __forceinline__ void cp16(void* dst, const void* src) {
    uint32_t d = smem_u32(dst);
    asm volatile("cp.async.cg.shared.global [%0], [%1], 16;" :: "r"(d), "l"(src));
}
#define CP_COMMIT() asm volatile("cp.async.commit_group;")
#define CP_WAIT1()  asm volatile("cp.async.wait_group 1;")

__device__ __forceinline__ float tf32_rna(float v) {
    uint32_t r;
    asm("cvt.rna.tf32.f32 %0, %1;" : "=r"(r) : "f"(v));
    return __uint_as_float(r);
}

__device__ __forceinline__ void mma_tf32(float* c, const uint32_t* a, const uint32_t* b) {
    asm volatile(
        "mma.sync.aligned.m16n8k8.row.col.f32.tf32.tf32.f32 "
        "{%0,%1,%2,%3}, {%4,%5,%6,%7}, {%8,%9}, {%0,%1,%2,%3};"
        : "+f"(c[0]), "+f"(c[1]), "+f"(c[2]), "+f"(c[3])
        : "r"(a[0]), "r"(a[1]), "r"(a[2]), "r"(a[3]), "r"(b[0]), "r"(b[1]));
}

// ---------------- GEMM config (exact round-3 configuration) ----------------
#define BM 128
#define BN 128
#define BK 32
#define PITCH 36                          // floats; conflict-free frag reads
#define STAGE_FLOATS (2 * 128 * PITCH)    // A+B per stage = 9216 floats (36 KB)
#define GEMM_SMEM (2 * STAGE_FLOATS * 4)  // 73728 bytes

// ---------------------------------------------------------------------------
// Norms + tf32 pre-rounding (one float4 per thread)  [unchanged from R6]
// ---------------------------------------------------------------------------
__global__ void __launch_bounds__(256) norms_kernel(const float* __restrict__ X,
                                                    const float* __restrict__ Y) {
    __shared__ float s1[256], s2[256];
    const int row = blockIdx.x;
    const int isY = blockIdx.y;
    const int tid = threadIdx.x;
    const float4* p4 = (const float4*)((isY ? Y : X) + (size_t)row * DDIM);
    float4* pr4 = (float4*)((isY ? g_yr : g_xr) + (size_t)row * DDIM);

    float4 v = p4[tid];
    float4 r;
    r.x = tf32_rna(v.x); r.y = tf32_rna(v.y); r.z = tf32_rna(v.z); r.w = tf32_rna(v.w);
    pr4[tid] = r;

    float a, b = 0.0f;
    if (isY) {
        a = v.x * v.x + v.y * v.y + v.z * v.z + v.w * v.w;
        b = v.x + v.y + v.z + v.w;
    } else {
        float ex = v.x + EPSV, ey = v.y + EPSV, ez = v.z + EPSV, ew = v.w + EPSV;
        a = ex * ex + ey * ey + ez * ez + ew * ew;
    }
    s1[tid] = a; s2[tid] = b;
    __syncthreads();
    for (int off = 128; off; off >>= 1) {
        if (tid < off) { s1[tid] += s1[tid + off]; s2[tid] += s2[tid + off]; }
        __syncthreads();
    }
    if (tid == 0) {
        if (isY) { g_ny[row] = s1[0]; g_sy[row] = s2[0]; }
        else     { g_nx[row] = s1[0]; }
    }
}

// ---------------------------------------------------------------------------
// tf32 mma.sync GEMM + distance epilogue (writes dist AND distT).
// [byte-identical to round-6 version]
// ---------------------------------------------------------------------------
__device__ __forceinline__ void issue_stage(float* sA, float* sB,
                                            const float* gA, const float* gB, int tid) {
#pragma unroll
    for (int i = 0; i < 4; i++) {
        const int idx = tid + i * 256;      // 0..1023
        const int r = idx >> 3;             // row 0..127
        const int c = (idx & 7) * 4;        // float col 0,4,..,28
        cp16(sA + r * PITCH + c, gA + (size_t)r * DDIM + c);
        cp16(sB + r * PITCH + c, gB + (size_t)r * DDIM + c);
    }
}

__global__ void __launch_bounds__(256, 2) gemm_mma_kernel() {
    extern __shared__ float smf[];
    const int tid = threadIdx.x;
    const int wid = tid >> 5;
    const int lane = tid & 31;
    const int wm = wid & 3;
    const int wn = wid >> 2;
    const int g = lane >> 2;
    const int t = lane & 3;
    const int bi = blockIdx.y * BM;
    const int bj = blockIdx.x * BN;

    const float* gA = g_xr + (size_t)bi * DDIM;
    const float* gB = g_yr + (size_t)bj * DDIM;

    float acc[2][8][4];
#pragma unroll
    for (int mi = 0; mi < 2; mi++)
#pragma unroll
        for (int ni = 0; ni < 8; ni++)
#pragma unroll
            for (int e = 0; e < 4; e++) acc[mi][ni][e] = 0.0f;

    issue_stage(smf, smf + 128 * PITCH, gA, gB, tid);
    CP_COMMIT();
    issue_stage(smf + STAGE_FLOATS, smf + STAGE_FLOATS + 128 * PITCH,
                gA + BK, gB + BK, tid);
    CP_COMMIT();

    const int NCHUNK = DDIM / BK;
    for (int c = 0; c < NCHUNK; c++) {
        const int buf = c & 1;
        CP_WAIT1();
        __syncthreads();
        const uint32_t* sA = (const uint32_t*)(smf + buf * STAGE_FLOATS);
        const uint32_t* sB = sA + 128 * PITCH;

#pragma unroll
        for (int ks = 0; ks < 4; ks++) {
            const int k0 = ks * 8;
            uint32_t a[2][4], b[8][2];
#pragma unroll
            for (int mi = 0; mi < 2; mi++) {
                const int r0 = wm * 32 + mi * 16;
                a[mi][0] = sA[(r0 + g) * PITCH + k0 + t];
                a[mi][1] = sA[(r0 + g + 8) * PITCH + k0 + t];
                a[mi][2] = sA[(r0 + g) * PITCH + k0 + t + 4];
                a[mi][3] = sA[(r0 + g + 8) * PITCH + k0 + t + 4];
            }
#pragma unroll
            for (int ni = 0; ni < 8; ni++) {
                const int c0 = wn * 64 + ni * 8;
                b[ni][0] = sB[(c0 + g) * PITCH + k0 + t];
                b[ni][1] = sB[(c0 + g) * PITCH + k0 + t + 4];
            }
#pragma unroll
            for (int mi = 0; mi < 2; mi++)
#pragma unroll
                for (int ni = 0; ni < 8; ni++)
                    mma_tf32(acc[mi][ni], a[mi], b[ni]);
        }
        __syncthreads();
        if (c + 2 < NCHUNK)
            issue_stage(smf + buf * STAGE_FLOATS,
                        smf + buf * STAGE_FLOATS + 128 * PITCH,
                        gA + (c + 2) * BK, gB + (c + 2) * BK, tid);
        CP_COMMIT();
    }

    __syncthreads();
    float* tile = smf;                       // 128 x 129
    float* nx_s = smf + 128 * 129;
    float* ny_s = nx_s + 128;
    float* sy_s = ny_s + 128;
    if (tid < 128) {
        nx_s[tid] = g_nx[bi + tid];
        ny_s[tid] = g_ny[bj + tid];
        sy_s[tid] = g_sy[bj + tid];
    }
    __syncthreads();

#pragma unroll
    for (int mi = 0; mi < 2; mi++) {
        const int r0 = wm * 32 + mi * 16 + g;
#pragma unroll
        for (int ni = 0; ni < 8; ni++) {
            const int c0 = wn * 64 + ni * 8 + 2 * t;
#pragma unroll
            for (int e = 0; e < 4; e++) {
                const int row = r0 + (e >> 1) * 8;
                const int col = c0 + (e & 1);
                float sq = nx_s[row] + ny_s[col] - 2.0f * acc[mi][ni][e]
                           - 2.0f * EPSV * sy_s[col];
                tile[row * 129 + col] = sqrtf(fmaxf(sq, 0.0f));
            }
        }
    }
    __syncthreads();

    for (int i = tid; i < 128 * 32; i += 256) {
        const int rr = i >> 5;
        const int c4 = (i & 31) << 2;
        float4 v;
        v.x = tile[rr * 129 + c4 + 0];
        v.y = tile[rr * 129 + c4 + 1];
        v.z = tile[rr * 129 + c4 + 2];
        v.w = tile[rr * 129 + c4 + 3];
        *(float4*)&g_dist[(size_t)(bi + rr) * BDIM + bj + c4] = v;
    }
    for (int i = tid; i < 128 * 128; i += 256) {
        const int rr = i & 127;
        const int cc = i >> 7;
        g_distT[(size_t)(bj + cc) * BDIM + bi + rr] = tile[rr * 129 + cc];
    }
}

// ---------------------------------------------------------------------------
// Per-row loss, exact K-th order statistic. All values live in registers
// (16 per thread). Pass 0 (top byte, pathologically skewed) replaced by an
// atomic-free digit walk from the row min; passes 1-3 histogram from regs
// with plain smem atomics (digits are spread there). Two-level shuffle
// reductions; warp-0 shuffle scan for digit pick.
// grid (BDIM, 2): y=0 rows of dist (loss_xy), y=1 rows of distT (loss_yx).
// ---------------------------------------------------------------------------
__global__ void __launch_bounds__(256) select_kernel() {
    __shared__ unsigned hist[256];
    __shared__ float wf[8];
    __shared__ unsigned wu[8];
    __shared__ float wm8[8];
    __shared__ float s_t;
    __shared__ unsigned s_ctot;
    __shared__ float s_sall;
    __shared__ float s_min;
    __shared__ unsigned s_cd;
    __shared__ unsigned s_prefix, s_remk;

    const int row = blockIdx.x;
    const int tid = threadIdx.x;
    const int wid = tid >> 5;
    const int lane = tid & 31;
    const float* mat = blockIdx.y ? g_distT : g_dist;
    float* rl = g_rl + blockIdx.y * BDIM;
    const float4* rp4 = (const float4*)(mat + (size_t)row * BDIM);

    // 16 values per thread, registers only
    float4 rv[4];
#pragma unroll
    for (int q = 0; q < 4; q++) rv[q] = rp4[tid + q * 256];

    if (tid == 0) s_t = MARGINV + mat[(size_t)row * BDIM + row];

    // patch diagonal in the owning thread's register copy
    {
        const int di = row >> 2;
        if ((di & 255) == tid) ((float*)&rv[di >> 8])[row & 3] = BIGV;
    }
    __syncthreads();
    const float t = s_t;

    // ---- fused sweep: hinge count/sum vs t, and row min (registers) ----
    unsigned c = 0; float s = 0.0f; float mn = BIGV;
#pragma unroll
    for (int q = 0; q < 4; q++) {
        const float* f = (const float*)&rv[q];
#pragma unroll
        for (int e = 0; e < 4; e++) {
            const float v = f[e];
            if (v < t) { c++; s += t - v; }
            mn = fminf(mn, v);
        }
    }
#pragma unroll
    for (int off = 16; off; off >>= 1) {
        c += __shfl_down_sync(0xFFFFFFFFu, c, off);
        s += __shfl_down_sync(0xFFFFFFFFu, s, off);
        mn = fminf(mn, __shfl_down_sync(0xFFFFFFFFu, mn, off));
    }
    if (lane == 0) { wu[wid] = c; wf[wid] = s; wm8[wid] = mn; }
    __syncthreads();
    if (tid == 0) {
        unsigned ct = 0; float st = 0.0f; float mt = BIGV;
#pragma unroll
        for (int w = 0; w < 8; w++) { ct += wu[w]; st += wf[w]; mt = fminf(mt, wm8[w]); }
        s_ctot = ct; s_sall = st; s_min = mt;
    }
    __syncthreads();

    if (s_ctot <= KSEL) {
        if (tid == 0) rl[row] = s_sall;
        return;
    }

    // ---- pass 0: atomic-free top-byte digit walk from the min ----
    unsigned remk = KSEL;
    unsigned D = __float_as_uint(s_min) >> 24;
    for (;;) {
        unsigned cd = 0;
#pragma unroll
        for (int q = 0; q < 4; q++) {
            const float* f = (const float*)&rv[q];
#pragma unroll
            for (int e = 0; e < 4; e++)
                cd += ((__float_as_uint(f[e]) >> 24) == D);
        }
#pragma unroll
        for (int off = 16; off; off >>= 1)
            cd += __shfl_down_sync(0xFFFFFFFFu, cd, off);
        if (lane == 0) wu[wid] = cd;
        __syncthreads();
        if (tid == 0) {
            unsigned ct = 0;
#pragma unroll
            for (int w = 0; w < 8; w++) ct += wu[w];
            s_cd = ct;
        }
        __syncthreads();
        const unsigned cdtot = s_cd;
        __syncthreads();
        if (cdtot >= remk) break;
        remk -= cdtot;
        D++;
    }
    unsigned prefix = D << 24;

    // ---- passes 1-3: register-sourced histograms, plain atomics ----
#pragma unroll
    for (int pass = 1; pass < 4; pass++) {
        const int shift = 24 - 8 * pass;
        hist[tid] = 0;
        __syncthreads();
        const unsigned pmask = 0xFFFFFFFFu << (shift + 8);
#pragma unroll
        for (int q = 0; q < 4; q++) {
            const float* f = (const float*)&rv[q];
#pragma unroll
            for (int e = 0; e < 4; e++) {
                const unsigned b = __float_as_uint(f[e]);
                if ((b & pmask) == prefix) atomicAdd(&hist[(b >> shift) & 255], 1u);
            }
        }
        __syncthreads();
        // warp-0 shuffle scan over 256 bins (8 per lane)
        if (tid < 32) {
            unsigned loc[8]; unsigned lsum = 0;
#pragma unroll
            for (int j = 0; j < 8; j++) { loc[j] = hist[tid * 8 + j]; lsum += loc[j]; }
            unsigned incl = lsum;
#pragma unroll
            for (int off = 1; off < 32; off <<= 1) {
                unsigned y = __shfl_up_sync(0xFFFFFFFFu, incl, off);
                if (tid >= off) incl += y;
            }
            const unsigned excl = incl - lsum;
            if (excl < remk && incl >= remk) {
                unsigned cum = excl;
#pragma unroll
                for (int j = 0; j < 8; j++) {
                    if (cum + loc[j] >= remk) {
                        s_prefix = prefix | ((unsigned)(tid * 8 + j) << shift);
                        s_remk = remk - cum;
                        break;
                    }
                    cum += loc[j];
                }
            }
        }
        __syncthreads();
        prefix = s_prefix;
        remk = s_remk;
        __syncthreads();
    }
    const float theta = __uint_as_float(prefix);

    // ---- final: sum/count strictly below theta (registers) ----
    unsigned cl = 0; float sl = 0.0f;
#pragma unroll
    for (int q = 0; q < 4; q++) {
        const float* f = (const float*)&rv[q];
#pragma unroll
        for (int e = 0; e < 4; e++) {
            const float v = f[e];
            if (v < theta) { cl++; sl += v; }
        }
    }
#pragma unroll
    for (int off = 16; off; off >>= 1) {
        cl += __shfl_down_sync(0xFFFFFFFFu, cl, off);
        sl += __shfl_down_sync(0xFFFFFFFFu, sl, off);
    }
    if (lane == 0) { wu[wid] = cl; wf[wid] = sl; }
    __syncthreads();
    if (tid == 0) {
        unsigned ct = 0; float st = 0.0f;
#pragma unroll
        for (int w = 0; w < 8; w++) { ct += wu[w]; st += wf[w]; }
        rl[row] = (float)KSEL * t - st - (float)(KSEL - ct) * theta;
    }
}

// ---------------------------------------------------------------------------
__global__ void finalize_kernel(float* __restrict__ out) {
    __shared__ float sm[256];
    const int which = blockIdx.x;
    float s = 0.0f;
    for (int i = threadIdx.x; i < BDIM; i += 256) s += g_rl[which * BDIM + i];
    sm[threadIdx.x] = s;
    __syncthreads();
    for (int off = 128; off; off >>= 1) {
        if (threadIdx.x < off) sm[threadIdx.x] += sm[threadIdx.x + off];
        __syncthreads();
    }
    if (threadIdx.x == 0) out[which] = sm[0] / ((float)BDIM * (float)KSEL);
}

// ---------------------------------------------------------------------------
extern "C" void kernel_launch(void* const* d_in, const int* in_sizes, int n_in,
                              void* d_out, int out_size) {
    const float* X = (const float*)d_in[0];
    const float* Y = (const float*)d_in[1];
    float* out = (float*)d_out;

    cudaFuncSetAttribute(gemm_mma_kernel, cudaFuncAttributeMaxDynamicSharedMemorySize,
                         GEMM_SMEM);

    norms_kernel<<<dim3(BDIM, 2), 256>>>(X, Y);
    gemm_mma_kernel<<<dim3(BDIM / BN, BDIM / BM), 256, GEMM_SMEM>>>();
    select_kernel<<<dim3(BDIM, 2), 256>>>();
    finalize_kernel<<<2, 256>>>(out);
}